// round 3
// baseline (speedup 1.0000x reference)
#include <cuda_runtime.h>
#include <cstdint>

// Problem constants
#define N_IMG   4
#define N_ANC   15
#define FH      320
#define FW      320
#define HW      (FH * FW)           // 102400
#define PER_IMG (N_ANC * HW)        // 1536000
#define PRE_TOPN  1000
#define POST_TOPN 100
#define NMS_TH    0.7f
#define BBOX_CLIP 4.135166556742356f   // log(1000/16)
#define STRIDE    4.0f                  // 1/0.25

#define NB   16384      // histogram bins over [0,1)
#define CAP  4096       // candidate capacity per image
#define SORT_N 4096

typedef unsigned long long u64;
typedef unsigned int u32;

// ---------------- scratch (device globals; no allocation allowed) -------------
__device__ float g_scores[N_IMG * PER_IMG];     // masked scores, input layout (a,h,w)
__device__ u32   g_hist[N_IMG * NB];
__device__ int   g_thresh[N_IMG];
__device__ int   g_cnt[N_IMG];
__device__ u64   g_cand[N_IMG * CAP];

// ---------------- shared box decode ------------------------------------------
__device__ __forceinline__ void decode_box(
    int a, int h, int w, int n,
    const float* __restrict__ deltas,
    const float* __restrict__ cell_anchors,
    float im_h, float im_w,
    float& x1, float& y1, float& x2, float& y2)
{
    float shx = (float)w * STRIDE;
    float shy = (float)h * STRIDE;
    float ax1 = shx + cell_anchors[a * 4 + 0];
    float ay1 = shy + cell_anchors[a * 4 + 1];
    float ax2 = shx + cell_anchors[a * 4 + 2];
    float ay2 = shy + cell_anchors[a * 4 + 3];
    float aw  = ax2 - ax1;
    float ah  = ay2 - ay1;
    float acx = ax1 + 0.5f * aw;
    float acy = ay1 + 0.5f * ah;

    const float* db = deltas + ((size_t)n * N_ANC * 4 + (size_t)a * 4) * HW
                             + (size_t)h * FW + w;
    float d0 = db[0];
    float d1 = db[HW];
    float d2 = db[2 * HW];
    float d3 = db[3 * HW];

    float dw = fminf(d2, BBOX_CLIP);
    float dh = fminf(d3, BBOX_CLIP);
    float pcx = d0 * aw + acx;
    float pcy = d1 * ah + acy;
    float pw  = expf(dw) * aw;
    float ph  = expf(dh) * ah;

    x1 = fminf(fmaxf(pcx - 0.5f * pw, 0.0f), im_w);
    y1 = fminf(fmaxf(pcy - 0.5f * ph, 0.0f), im_h);
    x2 = fminf(fmaxf(pcx + 0.5f * pw, 0.0f), im_w);
    y2 = fminf(fmaxf(pcy + 0.5f * ph, 0.0f), im_h);
}

// ---------------- K0: zero scratch -------------------------------------------
__global__ void k_zero()
{
    int i = blockIdx.x * blockDim.x + threadIdx.x;
    if (i < N_IMG * NB) g_hist[i] = 0u;
    if (i < N_IMG)      g_cnt[i] = 0;
}

// ---------------- K1: masked scores + histogram ------------------------------
__global__ void k_score_hist(const float* __restrict__ scores,
                             const float* __restrict__ deltas,
                             const float* __restrict__ im_info,
                             const float* __restrict__ cell_anchors)
{
    int n = blockIdx.y;
    int t = blockIdx.x * blockDim.x + threadIdx.x;
    if (t >= PER_IMG) return;

    int a  = t / HW;
    int hw = t - a * HW;
    int h  = hw / FW;
    int w  = hw - h * FW;

    float s = scores[(size_t)n * PER_IMG + t];
    float im_h = __ldg(&im_info[n * 3 + 0]);
    float im_w = __ldg(&im_info[n * 3 + 1]);

    float x1, y1, x2, y2;
    decode_box(a, h, w, n, deltas, cell_anchors, im_h, im_w, x1, y1, x2, y2);

    bool valid = (x2 > x1) && (y2 > y1);
    g_scores[(size_t)n * PER_IMG + t] = valid ? s : __int_as_float(0xff800000);
    if (valid) {
        int bin = (int)(s * (float)NB);
        bin = min(max(bin, 0), NB - 1);
        atomicAdd(&g_hist[n * NB + bin], 1u);
    }
}

// ---------------- K2: per-image threshold bin --------------------------------
__global__ void k_thresh()
{
    int n = blockIdx.x;
    __shared__ u32 partial[512];
    int tid = threadIdx.x;   // 512 threads

    // chunk tid covers 32 bins, counted from the TOP
    int hi = NB - 32 * tid;
    int lo = hi - 32;
    u32 sum = 0;
    for (int b = lo; b < hi; b++) sum += g_hist[n * NB + b];
    partial[tid] = sum;
    __syncthreads();

    if (tid == 0) {
        u32 cum = 0;
        int thresh = 0;
        for (int c = 0; c < 512; c++) {
            if (cum + partial[c] >= PRE_TOPN) {
                int top = NB - 32 * c;
                for (int b = top - 1; b >= top - 32; b--) {
                    cum += g_hist[n * NB + b];
                    if (cum >= PRE_TOPN) { thresh = b; break; }
                }
                break;
            }
            cum += partial[c];
        }
        g_thresh[n] = thresh;
    }
}

// ---------------- K3: collect candidates above threshold ---------------------
__global__ void k_collect()
{
    int n = blockIdx.y;
    int t = blockIdx.x * blockDim.x + threadIdx.x;
    if (t >= PER_IMG) return;

    float s = g_scores[(size_t)n * PER_IMG + t];
    if (!(s >= 0.0f)) return;   // -inf masked

    int bin = (int)(s * (float)NB);
    bin = min(max(bin, 0), NB - 1);
    if (bin < __ldg(&g_thresh[n])) return;

    int p = atomicAdd(&g_cnt[n], 1);
    if (p < CAP) {
        int a  = t / HW;
        int hw = t - a * HW;
        u32 idx = (u32)hw * N_ANC + (u32)a;   // (h,w,a) flat candidate index
        g_cand[(size_t)n * CAP + p] = ((u64)__float_as_uint(s) << 32) | (0xFFFFFFFFu - idx);
    }
}

// ---------------- K4: per-image sort + decode + NMS + output -----------------
__global__ void __launch_bounds__(1024, 1)
k_finalize(const float* __restrict__ deltas,
           const float* __restrict__ im_info,
           const float* __restrict__ cell_anchors,
           float* __restrict__ out)   // [400*5 rois][400 probs]
{
    extern __shared__ unsigned char smem_raw[];
    u64*   keys = (u64*)smem_raw;                     // SORT_N
    float* bx1  = (float*)(keys + SORT_N);            // 1024 each
    float* by1  = bx1 + 1024;
    float* bx2  = by1 + 1024;
    float* by2  = bx2 + 1024;
    float* barea= by2 + 1024;
    float* bscr = barea + 1024;
    u32*   sup  = (u32*)(bscr + 1024);                // 32 words
    int*   keep_list = (int*)(sup + 32);              // 128 ints

    int n   = blockIdx.x;
    int tid = threadIdx.x;
    int cnt = min(g_cnt[n], CAP);

    // load + pad keys
    for (int i = tid; i < SORT_N; i += 1024)
        keys[i] = (i < cnt) ? g_cand[(size_t)n * CAP + i] : 0ull;
    if (tid < 32) sup[tid] = (tid == 31) ? 0xFFFFFF00u : 0u;  // kill pad lanes 1000..1023
    __syncthreads();

    // bitonic sort, descending
    for (int k = 2; k <= SORT_N; k <<= 1) {
        for (int j = k >> 1; j > 0; j >>= 1) {
            for (int i = tid; i < SORT_N; i += 1024) {
                int ixj = i ^ j;
                if (ixj > i) {
                    u64 va = keys[i], vb = keys[ixj];
                    bool desc = ((i & k) == 0);
                    if (desc ? (va < vb) : (va > vb)) { keys[i] = vb; keys[ixj] = va; }
                }
            }
            __syncthreads();
        }
    }

    // decode top-1000 boxes
    float im_h = __ldg(&im_info[n * 3 + 0]);
    float im_w = __ldg(&im_info[n * 3 + 1]);
    if (tid < PRE_TOPN) {
        u64 key = keys[tid];
        u32 sbits = (u32)(key >> 32);
        if (sbits == 0u) {                 // pad / empty slot — suppress
            bx1[tid] = by1[tid] = bx2[tid] = by2[tid] = 0.0f;
            barea[tid] = 0.0f; bscr[tid] = 0.0f;
            atomicOr(&sup[tid >> 5], 1u << (tid & 31));
        } else {
            u32 idx = 0xFFFFFFFFu - (u32)key;
            int a  = idx % N_ANC;
            int hw = idx / N_ANC;
            int h  = hw / FW;
            int w  = hw - h * FW;
            float x1, y1, x2, y2;
            decode_box(a, h, w, n, deltas, cell_anchors, im_h, im_w, x1, y1, x2, y2);
            bx1[tid] = x1; by1[tid] = y1; bx2[tid] = x2; by2[tid] = y2;
            barea[tid] = (x2 - x1) * (y2 - y1);
            bscr[tid] = __uint_as_float(sbits);
        }
    }
    __syncthreads();

    // greedy NMS with early exit at POST_TOPN keepers
    int kept = 0;
    int i = 0;
    while (i < PRE_TOPN && kept < POST_TOPN) {
        u32 word = sup[i >> 5];
        u32 avail = ~word & (0xFFFFFFFFu << (i & 31));
        if (!avail) { i = ((i >> 5) + 1) << 5; continue; }
        i = (i & ~31) + __ffs(avail) - 1;

        // accept box i
        if (tid == 0) keep_list[kept] = i;
        float xi1 = bx1[i], yi1 = by1[i], xi2 = bx2[i], yi2 = by2[i];
        float ai  = barea[i];
        int j = i + 1 + tid;
        if (j < PRE_TOPN) {
            float xx1 = fmaxf(xi1, bx1[j]);
            float yy1 = fmaxf(yi1, by1[j]);
            float xx2 = fminf(xi2, bx2[j]);
            float yy2 = fminf(yi2, by2[j]);
            float inter = fmaxf(xx2 - xx1, 0.0f) * fmaxf(yy2 - yy1, 0.0f);
            float uni = ai + barea[j] - inter;
            float iou = (uni > 0.0f) ? inter / fmaxf(uni, 1e-12f) : 0.0f;
            if (iou > NMS_TH) atomicOr(&sup[j >> 5], 1u << (j & 31));
        }
        __syncthreads();
        kept++;
        i++;
    }
    __syncthreads();

    // write outputs: rois at [0, 2000), probs at [2000, 2400)
    float* out_rois  = out;
    float* out_probs = out + (size_t)N_IMG * POST_TOPN * 5;
    if (tid < POST_TOPN) {
        float* row = out_rois + ((size_t)n * POST_TOPN + tid) * 5;
        if (tid < kept) {
            int ki = keep_list[tid];
            row[0] = (float)n;
            row[1] = bx1[ki]; row[2] = by1[ki]; row[3] = bx2[ki]; row[4] = by2[ki];
            out_probs[n * POST_TOPN + tid] = bscr[ki];
        } else {
            row[0] = 0.0f; row[1] = 0.0f; row[2] = 0.0f; row[3] = 0.0f; row[4] = 0.0f;
            out_probs[n * POST_TOPN + tid] = 0.0f;
        }
    }
}

// ---------------- host launcher ----------------------------------------------
extern "C" void kernel_launch(void* const* d_in, const int* in_sizes, int n_in,
                              void* d_out, int out_size)
{
    const float* scores       = (const float*)d_in[0];
    const float* bbox_deltas  = (const float*)d_in[1];
    const float* im_info      = (const float*)d_in[2];
    const float* cell_anchors = (const float*)d_in[3];
    float* out = (float*)d_out;

    size_t fin_smem = (size_t)SORT_N * 8 + 6 * 1024 * 4 + 32 * 4 + 128 * 4;
    cudaFuncSetAttribute(k_finalize, cudaFuncAttributeMaxDynamicSharedMemorySize,
                         (int)fin_smem);

    // K0: zero histogram + counters
    {
        int total = N_IMG * NB;
        k_zero<<<(total + 255) / 256, 256>>>();
    }
    // K1: masked scores + histogram
    {
        dim3 grid((PER_IMG + 255) / 256, N_IMG);
        k_score_hist<<<grid, 256>>>(scores, bbox_deltas, im_info, cell_anchors);
    }
    // K2: per-image threshold
    k_thresh<<<N_IMG, 512>>>();
    // K3: collect candidates
    {
        dim3 grid((PER_IMG + 255) / 256, N_IMG);
        k_collect<<<grid, 256>>>();
    }
    // K4: sort + NMS + output (one block per image)
    k_finalize<<<N_IMG, 1024, fin_smem>>>(bbox_deltas, im_info, cell_anchors, out);
}

// round 7
// speedup vs baseline: 1.6739x; 1.6739x over previous
#include <cuda_runtime.h>
#include <cstdint>

// Problem constants
#define N_IMG   4
#define N_ANC   15
#define FH      320
#define FW      320
#define HW      (FH * FW)           // 102400
#define PER_IMG (N_ANC * HW)        // 1536000
#define PRE_TOPN  1000
#define POST_TOPN 100
#define NMS_TH    0.7f
#define BBOX_CLIP 4.135166556742356f   // log(1000/16)
#define STRIDE    4.0f                  // 1/0.25

#define NB     16384    // histogram bins over [0,1)
#define CAP    2048     // candidate capacity per image
#define SORT_N 2048

typedef unsigned long long u64;
typedef unsigned int u32;

// ---------------- scratch (device globals; no allocation allowed) -------------
__device__ u32   g_hist[N_IMG * NB];
__device__ int   g_thresh[N_IMG];
__device__ int   g_cnt[N_IMG];
__device__ u64   g_cand[N_IMG * CAP];

// ---------------- precise box decode (finalize path; matches reference) -------
__device__ __forceinline__ void decode_box(
    int a, int h, int w, int n,
    const float* __restrict__ deltas,
    const float* __restrict__ cell_anchors,
    float im_h, float im_w,
    float& x1, float& y1, float& x2, float& y2)
{
    float shx = (float)w * STRIDE;
    float shy = (float)h * STRIDE;
    float ax1 = shx + cell_anchors[a * 4 + 0];
    float ay1 = shy + cell_anchors[a * 4 + 1];
    float ax2 = shx + cell_anchors[a * 4 + 2];
    float ay2 = shy + cell_anchors[a * 4 + 3];
    float aw  = ax2 - ax1;
    float ah  = ay2 - ay1;
    float acx = ax1 + 0.5f * aw;
    float acy = ay1 + 0.5f * ah;

    const float* db = deltas + ((size_t)n * N_ANC * 4 + (size_t)a * 4) * HW
                             + (size_t)h * FW + w;
    float d0 = db[0];
    float d1 = db[HW];
    float d2 = db[2 * HW];
    float d3 = db[3 * HW];

    float dw = fminf(d2, BBOX_CLIP);
    float dh = fminf(d3, BBOX_CLIP);
    float pcx = d0 * aw + acx;
    float pcy = d1 * ah + acy;
    float pw  = expf(dw) * aw;
    float ph  = expf(dh) * ah;

    x1 = fminf(fmaxf(pcx - 0.5f * pw, 0.0f), im_w);
    y1 = fminf(fmaxf(pcy - 0.5f * ph, 0.0f), im_h);
    x2 = fminf(fmaxf(pcx + 0.5f * pw, 0.0f), im_w);
    y2 = fminf(fmaxf(pcy + 0.5f * ph, 0.0f), im_h);
}

// fast validity check (__expf; validity only flips via clipping degeneracy,
// which is robust to ~1e-6 perturbation)
__device__ __forceinline__ bool box_valid(
    float shx, float shy, float c0, float c1, float aw, float ah,
    float d0, float d1, float d2, float d3, float im_h, float im_w)
{
    float acx = shx + c0 + 0.5f * aw;
    float acy = shy + c1 + 0.5f * ah;
    float dw = fminf(d2, BBOX_CLIP);
    float dh = fminf(d3, BBOX_CLIP);
    float pcx = d0 * aw + acx;
    float pcy = d1 * ah + acy;
    float pw  = __expf(dw) * aw;
    float ph  = __expf(dh) * ah;
    float x1 = fminf(fmaxf(pcx - 0.5f * pw, 0.0f), im_w);
    float y1 = fminf(fmaxf(pcy - 0.5f * ph, 0.0f), im_h);
    float x2 = fminf(fmaxf(pcx + 0.5f * pw, 0.0f), im_w);
    float y2 = fminf(fmaxf(pcy + 0.5f * ph, 0.0f), im_h);
    return (x2 > x1) && (y2 > y1);
}

// ---------------- K0: zero scratch -------------------------------------------
__global__ void k_zero()
{
    int i = blockIdx.x * blockDim.x + threadIdx.x;
    if (i < N_IMG * NB) g_hist[i] = 0u;
    if (i < N_IMG)      g_cnt[i] = 0;
}

// ---------------- K1: valid-score histogram (float4 per thread) --------------
__global__ void k_hist(const float* __restrict__ scores,
                       const float* __restrict__ deltas,
                       const float* __restrict__ im_info,
                       const float* __restrict__ cell_anchors)
{
    int n = blockIdx.y;
    int i = blockIdx.x * blockDim.x + threadIdx.x;
    int t = i * 4;
    if (t >= PER_IMG) return;

    int a  = t / HW;
    int hw = t - a * HW;
    int h  = hw / FW;
    int w  = hw - h * FW;        // multiple of 4, same row for all 4 lanes

    float4 s4 = *(const float4*)(scores + (size_t)n * PER_IMG + t);
    const float* db = deltas + ((size_t)n * N_ANC * 4 + (size_t)a * 4) * HW
                             + (size_t)h * FW + w;
    float4 d0 = *(const float4*)(db);
    float4 d1 = *(const float4*)(db + HW);
    float4 d2 = *(const float4*)(db + 2 * HW);
    float4 d3 = *(const float4*)(db + 3 * HW);

    float im_h = __ldg(&im_info[n * 3 + 0]);
    float im_w = __ldg(&im_info[n * 3 + 1]);
    float c0 = __ldg(&cell_anchors[a * 4 + 0]);
    float c1 = __ldg(&cell_anchors[a * 4 + 1]);
    float c2 = __ldg(&cell_anchors[a * 4 + 2]);
    float c3 = __ldg(&cell_anchors[a * 4 + 3]);
    float aw = c2 - c0, ah = c3 - c1;
    float shy = (float)h * STRIDE;

    float sv[4] = {s4.x, s4.y, s4.z, s4.w};
    float e0[4] = {d0.x, d0.y, d0.z, d0.w};
    float e1[4] = {d1.x, d1.y, d1.z, d1.w};
    float e2[4] = {d2.x, d2.y, d2.z, d2.w};
    float e3[4] = {d3.x, d3.y, d3.z, d3.w};

#pragma unroll
    for (int l = 0; l < 4; l++) {
        float shx = (float)(w + l) * STRIDE;
        if (box_valid(shx, shy, c0, c1, aw, ah, e0[l], e1[l], e2[l], e3[l], im_h, im_w)) {
            int bin = (int)(sv[l] * (float)NB);
            bin = min(max(bin, 0), NB - 1);
            atomicAdd(&g_hist[n * NB + bin], 1u);
        }
    }
}

// ---------------- K2: per-image threshold bin --------------------------------
__global__ void k_thresh()
{
    int n = blockIdx.x;
    __shared__ u32 partial[512];
    int tid = threadIdx.x;   // 512 threads

    int hi = NB - 32 * tid;
    int lo = hi - 32;
    u32 sum = 0;
    for (int b = lo; b < hi; b++) sum += g_hist[n * NB + b];
    partial[tid] = sum;
    __syncthreads();

    if (tid == 0) {
        u32 cum = 0;
        int thresh = 0;
        for (int c = 0; c < 512; c++) {
            if (cum + partial[c] >= PRE_TOPN) {
                int top = NB - 32 * c;
                for (int b = top - 1; b >= top - 32; b--) {
                    cum += g_hist[n * NB + b];
                    if (cum >= PRE_TOPN) { thresh = b; break; }
                }
                break;
            }
            cum += partial[c];
        }
        g_thresh[n] = thresh;
    }
}

// ---------------- K3: collect candidates (float4 scores, rare decode) ---------
__global__ void k_collect(const float* __restrict__ scores,
                          const float* __restrict__ deltas,
                          const float* __restrict__ im_info,
                          const float* __restrict__ cell_anchors)
{
    int n = blockIdx.y;
    int i = blockIdx.x * blockDim.x + threadIdx.x;
    int t = i * 4;
    if (t >= PER_IMG) return;

    float4 s4 = *(const float4*)(scores + (size_t)n * PER_IMG + t);
    int thresh = __ldg(&g_thresh[n]);

    float sv[4] = {s4.x, s4.y, s4.z, s4.w};
    // fast reject: all four below threshold (the overwhelmingly common case)
    float thv_lo = (float)thresh * (1.0f / (float)NB) - 2e-4f;  // conservative
    if (sv[0] < thv_lo && sv[1] < thv_lo && sv[2] < thv_lo && sv[3] < thv_lo) return;

    int a  = t / HW;
    int hw = t - a * HW;
    int h  = hw / FW;
    int w  = hw - h * FW;

    float im_h = __ldg(&im_info[n * 3 + 0]);
    float im_w = __ldg(&im_info[n * 3 + 1]);
    float c0 = __ldg(&cell_anchors[a * 4 + 0]);
    float c1 = __ldg(&cell_anchors[a * 4 + 1]);
    float c2 = __ldg(&cell_anchors[a * 4 + 2]);
    float c3 = __ldg(&cell_anchors[a * 4 + 3]);
    float aw = c2 - c0, ah = c3 - c1;
    float shy = (float)h * STRIDE;

    const float* db = deltas + ((size_t)n * N_ANC * 4 + (size_t)a * 4) * HW
                             + (size_t)h * FW + w;

#pragma unroll
    for (int l = 0; l < 4; l++) {
        int bin = (int)(sv[l] * (float)NB);
        bin = min(max(bin, 0), NB - 1);
        if (bin < thresh) continue;
        // exact validity re-check (same math as K1)
        float d0 = db[l], d1 = db[l + HW], d2 = db[l + 2 * HW], d3 = db[l + 3 * HW];
        float shx = (float)(w + l) * STRIDE;
        if (!box_valid(shx, shy, c0, c1, aw, ah, d0, d1, d2, d3, im_h, im_w)) continue;

        int p = atomicAdd(&g_cnt[n], 1);
        if (p < CAP) {
            u32 idx = (u32)(hw + l) * N_ANC + (u32)a;  // (h,w,a) flat index
            g_cand[(size_t)n * CAP + p] =
                ((u64)__float_as_uint(sv[l]) << 32) | (0xFFFFFFFFu - idx);
        }
    }
}

// ---------------- K4: per-image sort + decode + NMS + output -----------------
__global__ void __launch_bounds__(1024, 1)
k_finalize(const float* __restrict__ deltas,
           const float* __restrict__ im_info,
           const float* __restrict__ cell_anchors,
           float* __restrict__ out)   // [400*5 rois][400 probs]
{
    __shared__ u64   keys[SORT_N];
    __shared__ float bx1[1024], by1[1024], bx2[1024], by2[1024];
    __shared__ float barea[1024], bscr[1024];
    __shared__ u32   sup[32];
    __shared__ int   keep_list[128];

    int n   = blockIdx.x;
    int tid = threadIdx.x;
    int cnt = min(g_cnt[n], CAP);

    // load + pad keys
    for (int i = tid; i < SORT_N; i += 1024)
        keys[i] = (i < cnt) ? g_cand[(size_t)n * CAP + i] : 0ull;
    if (tid < 32) sup[tid] = (tid == 31) ? 0xFFFFFF00u : 0u;  // kill pad lanes 1000..1023
    __syncthreads();

    // bitonic sort, descending
    for (int k = 2; k <= SORT_N; k <<= 1) {
        for (int j = k >> 1; j > 0; j >>= 1) {
            for (int i = tid; i < SORT_N; i += 1024) {
                int ixj = i ^ j;
                if (ixj > i) {
                    u64 va = keys[i], vb = keys[ixj];
                    bool desc = ((i & k) == 0);
                    if (desc ? (va < vb) : (va > vb)) { keys[i] = vb; keys[ixj] = va; }
                }
            }
            __syncthreads();
        }
    }

    // decode top-1000 boxes (precise expf path)
    float im_h = __ldg(&im_info[n * 3 + 0]);
    float im_w = __ldg(&im_info[n * 3 + 1]);
    if (tid < PRE_TOPN) {
        u64 key = keys[tid];
        u32 sbits = (u32)(key >> 32);
        if (sbits == 0u) {                 // pad / empty slot — suppress
            bx1[tid] = by1[tid] = bx2[tid] = by2[tid] = 0.0f;
            barea[tid] = 0.0f; bscr[tid] = 0.0f;
            atomicOr(&sup[tid >> 5], 1u << (tid & 31));
        } else {
            u32 idx = 0xFFFFFFFFu - (u32)key;
            int a  = idx % N_ANC;
            int hw = idx / N_ANC;
            int h  = hw / FW;
            int w  = hw - h * FW;
            float x1, y1, x2, y2;
            decode_box(a, h, w, n, deltas, cell_anchors, im_h, im_w, x1, y1, x2, y2);
            bx1[tid] = x1; by1[tid] = y1; bx2[tid] = x2; by2[tid] = y2;
            barea[tid] = (x2 - x1) * (y2 - y1);
            bscr[tid] = __uint_as_float(sbits);
        }
    }
    __syncthreads();

    // greedy NMS with early exit at POST_TOPN keepers
    int kept = 0;
    int i = 0;
    while (i < PRE_TOPN && kept < POST_TOPN) {
        u32 word = sup[i >> 5];
        u32 avail = ~word & (0xFFFFFFFFu << (i & 31));
        if (!avail) { i = ((i >> 5) + 1) << 5; continue; }
        i = (i & ~31) + __ffs(avail) - 1;

        if (tid == 0) keep_list[kept] = i;
        float xi1 = bx1[i], yi1 = by1[i], xi2 = bx2[i], yi2 = by2[i];
        float ai  = barea[i];
        int j = i + 1 + tid;
        if (j < PRE_TOPN) {
            float xx1 = fmaxf(xi1, bx1[j]);
            float yy1 = fmaxf(yi1, by1[j]);
            float xx2 = fminf(xi2, bx2[j]);
            float yy2 = fminf(yi2, by2[j]);
            float inter = fmaxf(xx2 - xx1, 0.0f) * fmaxf(yy2 - yy1, 0.0f);
            float uni = ai + barea[j] - inter;
            float iou = (uni > 0.0f) ? inter / fmaxf(uni, 1e-12f) : 0.0f;
            if (iou > NMS_TH) atomicOr(&sup[j >> 5], 1u << (j & 31));
        }
        __syncthreads();
        kept++;
        i++;
    }
    __syncthreads();

    // write outputs: rois at [0, 2000), probs at [2000, 2400)
    float* out_rois  = out;
    float* out_probs = out + (size_t)N_IMG * POST_TOPN * 5;
    if (tid < POST_TOPN) {
        float* row = out_rois + ((size_t)n * POST_TOPN + tid) * 5;
        if (tid < kept) {
            int ki = keep_list[tid];
            row[0] = (float)n;
            row[1] = bx1[ki]; row[2] = by1[ki]; row[3] = bx2[ki]; row[4] = by2[ki];
            out_probs[n * POST_TOPN + tid] = bscr[ki];
        } else {
            row[0] = 0.0f; row[1] = 0.0f; row[2] = 0.0f; row[3] = 0.0f; row[4] = 0.0f;
            out_probs[n * POST_TOPN + tid] = 0.0f;
        }
    }
}

// ---------------- host launcher ----------------------------------------------
extern "C" void kernel_launch(void* const* d_in, const int* in_sizes, int n_in,
                              void* d_out, int out_size)
{
    const float* scores       = (const float*)d_in[0];
    const float* bbox_deltas  = (const float*)d_in[1];
    const float* im_info      = (const float*)d_in[2];
    const float* cell_anchors = (const float*)d_in[3];
    float* out = (float*)d_out;

    // K0: zero histogram + counters
    {
        int total = N_IMG * NB;
        k_zero<<<(total + 255) / 256, 256>>>();
    }
    // K1: valid-score histogram (vectorized)
    {
        dim3 grid((PER_IMG / 4 + 255) / 256, N_IMG);
        k_hist<<<grid, 256>>>(scores, bbox_deltas, im_info, cell_anchors);
    }
    // K2: per-image threshold
    k_thresh<<<N_IMG, 512>>>();
    // K3: collect candidates (vectorized)
    {
        dim3 grid((PER_IMG / 4 + 255) / 256, N_IMG);
        k_collect<<<grid, 256>>>(scores, bbox_deltas, im_info, cell_anchors);
    }
    // K4: sort + NMS + output (one block per image)
    k_finalize<<<N_IMG, 1024>>>(bbox_deltas, im_info, cell_anchors, out);
}